// round 1
// baseline (speedup 1.0000x reference)
#include <cuda_runtime.h>

// Problem constants (fixed by the reference setup_inputs)
#define BB 64
#define SS 2048
#define DD 768
#define DD4 192          // DD / 4 (float4)
#define POOL 32
#define LL 8
#define TOPK 4
#define PROMPT_ROWS 41   // L + TOPK*L + 1
#define ROWS_OUT 2089    // PROMPT_ROWS + SS
#define SCHUNK 64
#define NCHUNK 32        // SS / SCHUNK
#define EPSV 1e-12f

// Scratch (no allocations allowed in kernel_launch)
__device__ float g_partial[NCHUNK * BB * DD];   // ~6.3 MB
__device__ int   g_topidx[BB * TOPK];

// ---------------------------------------------------------------------------
// Kernel 1: stream-copy x -> out tail, fused with per-(chunk,b,d) partial sums
// grid = (NCHUNK, BB), block = 192 threads (one float4 column each)
// ---------------------------------------------------------------------------
__global__ void k_copy_reduce(const float4* __restrict__ x,
                              float4* __restrict__ out) {
    const int b     = blockIdx.y;
    const int chunk = blockIdx.x;
    const int d4    = threadIdx.x;                   // 0..191

    const float4* xp = x   + ((size_t)b * SS + (size_t)chunk * SCHUNK) * DD4 + d4;
    float4*       op = out + ((size_t)b * ROWS_OUT + PROMPT_ROWS
                              + (size_t)chunk * SCHUNK) * DD4 + d4;

    float4 acc = make_float4(0.f, 0.f, 0.f, 0.f);
    #pragma unroll 8
    for (int s = 0; s < SCHUNK; s++) {
        float4 v = xp[(size_t)s * DD4];
        op[(size_t)s * DD4] = v;
        acc.x += v.x; acc.y += v.y; acc.z += v.z; acc.w += v.w;
    }
    ((float4*)g_partial)[((size_t)chunk * BB + b) * DD4 + d4] = acc;
}

// ---------------------------------------------------------------------------
// Kernel 2: deterministic reduce of partials -> query, cosine sims vs keys,
// top-4 selection (descending, lowest index on tie).  grid = BB, block = 256
// ---------------------------------------------------------------------------
__global__ void k_topk(const float* __restrict__ keys) {
    __shared__ float q[DD];
    __shared__ float sims[POOL];
    __shared__ float red[8];

    const int b   = blockIdx.x;
    const int tid = threadIdx.x;

    // Reduce 32 partials per d (each thread owns 3 d slots: 768 = 3*256)
    float local_sq = 0.f;
    #pragma unroll
    for (int i = 0; i < 3; i++) {
        const int d = tid + i * 256;
        float s = 0.f;
        #pragma unroll
        for (int c = 0; c < NCHUNK; c++)
            s += g_partial[((size_t)c * BB + b) * DD + d];
        s *= (1.0f / (float)SS);    // mean
        q[d] = s;
        local_sq += s * s;
    }
    // block reduce of ||q||^2
    #pragma unroll
    for (int o = 16; o > 0; o >>= 1)
        local_sq += __shfl_xor_sync(0xffffffffu, local_sq, o);
    if ((tid & 31) == 0) red[tid >> 5] = local_sq;
    __syncthreads();
    float qq = 0.f;
    #pragma unroll
    for (int i = 0; i < 8; i++) qq += red[i];

    // Cosine sims: warp w handles pools 4w..4w+3
    const int w = tid >> 5, lane = tid & 31;
    #pragma unroll
    for (int pp = 0; pp < 4; pp++) {
        const int p = w * 4 + pp;
        float aqk = 0.f, akk = 0.f;
        for (int d = lane; d < DD; d += 32) {
            const float k = keys[(size_t)p * DD + d];
            aqk += q[d] * k;
            akk += k * k;
        }
        #pragma unroll
        for (int o = 16; o > 0; o >>= 1) {
            aqk += __shfl_xor_sync(0xffffffffu, aqk, o);
            akk += __shfl_xor_sync(0xffffffffu, akk, o);
        }
        if (lane == 0)
            sims[p] = aqk * rsqrtf((qq + EPSV) * (akk + EPSV));
    }
    __syncthreads();

    // Serial top-4 (32 elements): strict > keeps lowest index on ties
    if (tid == 0) {
        unsigned used = 0;
        #pragma unroll
        for (int k = 0; k < TOPK; k++) {
            float best = -3.402823e38f; int bi = 0;
            for (int p = 0; p < POOL; p++) {
                if (!((used >> p) & 1u) && sims[p] > best) { best = sims[p]; bi = p; }
            }
            used |= 1u << bi;
            g_topidx[b * TOPK + k] = bi;
        }
    }
}

// ---------------------------------------------------------------------------
// Kernel 3: write the 41 prompt rows per batch:
// [ g_prompts[task_id] (8) | e_prompts[top4] (32) | cls (1) ]
// grid = (PROMPT_ROWS, BB), block = 192
// ---------------------------------------------------------------------------
__global__ void k_prompts(const float4* __restrict__ gp,
                          const float4* __restrict__ ep,
                          const float4* __restrict__ cls,
                          const int* __restrict__ task_id,
                          float4* __restrict__ out) {
    const int b  = blockIdx.y;
    const int r  = blockIdx.x;       // 0..40
    const int d4 = threadIdx.x;

    const float4* src;
    if (r < LL) {
        src = gp + ((size_t)task_id[0] * LL + r) * DD4;
    } else if (r < LL + TOPK * LL) {
        const int rr  = r - LL;
        const int idx = g_topidx[b * TOPK + (rr >> 3)];   // rr / L
        src = ep + ((size_t)idx * LL + (rr & 7)) * DD4;   // rr % L
    } else {
        src = cls;
    }
    out[((size_t)b * ROWS_OUT + r) * DD4 + d4] = src[d4];
}

// ---------------------------------------------------------------------------
extern "C" void kernel_launch(void* const* d_in, const int* in_sizes, int n_in,
                              void* d_out, int out_size) {
    const float4* x   = (const float4*)d_in[0];   // [64,2048,768]
    const float4* gp  = (const float4*)d_in[1];   // [10,8,768]
    const float4* ep  = (const float4*)d_in[2];   // [32,8,768]
    const float*  key = (const float*) d_in[3];   // [32,768]
    const float4* cls = (const float4*)d_in[4];   // [1,1,768]
    const int*    tid = (const int*)   d_in[5];   // scalar task_id
    float4* out = (float4*)d_out;

    k_copy_reduce<<<dim3(NCHUNK, BB), 192>>>(x, out);
    k_topk<<<BB, 256>>>(key);
    k_prompts<<<dim3(PROMPT_ROWS, BB), 192>>>(gp, ep, cls, tid, out);
}